// round 11
// baseline (speedup 1.0000x reference)
#include <cuda_runtime.h>
#include <cuda.h>
#include <cuda_bf16.h>
#include <cuda_fp8.h>
#include <math.h>
#include <stdint.h>
#include <dlfcn.h>

// ---- feature probe: tcgen05/cg2 need arch-specific (sm_103a) pass ----
#if defined(__CUDA_ARCH_FEAT_SM103_ALL) || \
    (defined(__CUDA_ARCH_SPECIFIC__) && (__CUDA_ARCH_SPECIFIC__ == 1030))
#define HAS_TC 1
#else
#define HAS_TC 0
#endif

// ---------------- problem constants ----------------
#define N_ROWS 4096
#define D_DIM  1024
#define TILE   256                         // 256x256 output tiles (cg2 pair)
#define NT     (N_ROWS / TILE)             // 16 column tiles -> 16 partials/row
#define NUM_TILES (NT * NT)                // 256
#define GRID_GEMM 128                      // 64 clusters of 2
#define NUM_CLUSTERS (GRID_GEMM / 2)       // 64
#define TILES_PER_CL (NUM_TILES / NUM_CLUSTERS)  // 4 (same col panel per cluster)
#define CHUNK_K 128                        // fp8: 128 elems = 128B per row chunk
#define NUM_CHUNKS (D_DIM / CHUNK_K)       // 8
#define STAGES 6                           // A stages

// FP8 scaling: store 64*v (e4m3), logits = acc / 4096
#define QSCALE 64.0f

// SMEM layout (per CTA)
#define SMEM_TMEM   0
#define SMEM_FULL   8       // 6 x 8B  (A stage full, leader)
#define SMEM_EMPTY  56      // 6 x 8B  (A stage empty, multicast)
#define SMEM_BFULL  104     // 8 x 8B  (B chunk full, leader)
#define SMEM_TDONE  168     // 2 x 8B  (tile MMA done, multicast)
#define SMEM_DFREE  184     // 2 x 8B  (TMEM buffer free, leader, count 8)
#define SMEM_B      1024                    // B panel: 8 chunks x 16KB = 128KB
#define B_CHUNK_BYTES 16384
#define SMEM_A      (SMEM_B + NUM_CHUNKS * B_CHUNK_BYTES)   // 132096
#define A_STAGE_BYTES 16384
#define SMEM_TOTAL  (SMEM_A + STAGES * A_STAGE_BYTES)       // 230400
#define A_EXPECT (2 * A_STAGE_BYTES)        // both CTAs -> leader barrier
#define B_CHUNK_EXPECT (2 * B_CHUNK_BYTES)  // both CTAs' halves of one chunk

// idesc: kind::f8f6f4, dtype F32 (bits[4:5]=1), atype=btype=E4M3 (0),
// N=256 (bits[17:23)), M_total=256 (bits[24:29))
#define MMA_IDESC ((1u<<4)|((TILE/8)<<17)|((TILE/16)<<24))

// SW128 K-major smem descriptor base (layout=2, version=1, SBO=64, LBO=1)
static __device__ constexpr uint64_t DESC_BASE =
    (uint64_t(2) << 61) | (uint64_t(1) << 46) | (uint64_t(64) << 32) | (uint64_t(1) << 16);

// ---------------- device scratch (no cudaMalloc allowed) ----------------
__device__ __align__(1024) unsigned char g_z1q[N_ROWS * D_DIM];
__device__ __align__(1024) unsigned char g_z2q[N_ROWS * D_DIM];
__device__ float    g_partial[N_ROWS * NT];
__device__ float    g_diag[N_ROWS];
__device__ double   g_blocksum[32];
__device__ unsigned g_ctr;    // zero-init; self-resetting each call

// ---------------- PTX helpers ----------------
__device__ __forceinline__ uint32_t smem_u32(const void* p) {
    uint32_t a;
    asm("{ .reg .u64 t; cvta.to.shared.u64 t, %1; cvt.u32.u64 %0, t; }" : "=r"(a) : "l"(p));
    return a;
}
__device__ __forceinline__ float ex2f(float x) {
    float y; asm("ex2.approx.f32 %0, %1;" : "=f"(y) : "f"(x)); return y;
}

#if HAS_TC
__device__ __forceinline__ uint32_t elect_one() {
    uint32_t p;
    asm volatile("{ .reg .pred p; elect.sync _|p, 0xFFFFFFFF; selp.b32 %0,1,0,p; }" : "=r"(p));
    return p;
}
__device__ __forceinline__ void mbar_init(uint32_t a, uint32_t cnt) {
    asm volatile("mbarrier.init.shared.b64 [%0], %1;" :: "r"(a), "r"(cnt) : "memory");
}
__device__ __forceinline__ void mbar_expect_tx(uint32_t a, uint32_t bytes) {
    asm volatile("mbarrier.arrive.expect_tx.shared.b64 _, [%0], %1;" :: "r"(a), "r"(bytes) : "memory");
}
__device__ __forceinline__ void mbar_arrive_leader(uint32_t a) {
    asm volatile("{ .reg .b32 la; and.b32 la, %0, 0xFEFFFFFF;\n"
                 "mbarrier.arrive.shared::cluster.b64 _, [la]; }" :: "r"(a) : "memory");
}
__device__ __forceinline__ void mbar_wait_acq(uint32_t a, uint32_t ph) {
    asm volatile("{ .reg .pred P;\n"
                 "W_%=: mbarrier.try_wait.parity.acquire.cta.shared::cta.b64 P, [%0], %1;\n"
                 "@!P bra W_%=; }" :: "r"(a), "r"(ph) : "memory");
}
__device__ __forceinline__ void mbar_wait_rlx(uint32_t a, uint32_t ph) {
    asm volatile("{ .reg .pred P;\n"
                 "W_%=: mbarrier.try_wait.parity.relaxed.cta.shared::cta.b64 P, [%0], %1;\n"
                 "@!P bra W_%=; }" :: "r"(a), "r"(ph) : "memory");
}
// cg2 TMA: both CTAs execute; complete_tx targets the LEADER's barrier (bit 24 cleared)
__device__ __forceinline__ void tma2d_cg2(uint32_t dst, const CUtensorMap* m, int x, int y, uint32_t mbar) {
    asm volatile("{ .reg .b32 lb; and.b32 lb, %4, 0xFEFFFFFF;\n"
                 "cp.async.bulk.tensor.2d.cta_group::2.shared::cluster.global.tile.mbarrier::complete_tx::bytes "
                 "[%0], [%1, {%2, %3}], [lb]; }"
                 :: "r"(dst), "l"(m), "r"(x), "r"(y), "r"(mbar) : "memory");
}
__device__ __forceinline__ void tc_alloc_cg2(uint32_t smem_res, uint32_t ncols) {
    asm volatile("tcgen05.alloc.cta_group::2.sync.aligned.shared::cta.b32 [%0], %1;"
                 :: "r"(smem_res), "r"(ncols) : "memory");
}
__device__ __forceinline__ void tc_dealloc_cg2(uint32_t tmem, uint32_t ncols) {
    asm volatile("tcgen05.dealloc.cta_group::2.sync.aligned.b32 %0, %1;" :: "r"(tmem), "r"(ncols));
}
__device__ __forceinline__ void tc_relinq_cg2() {
    asm volatile("tcgen05.relinquish_alloc_permit.cta_group::2.sync.aligned;");
}
__device__ __forceinline__ void tc_commit_mc_cg2(uint32_t mbar) {
    asm volatile("tcgen05.commit.cta_group::2.mbarrier::arrive::one.shared::cluster.multicast::cluster.b64 [%0], %1;"
                 :: "r"(mbar), "h"((uint16_t)3) : "memory");
}
__device__ __forceinline__ void tc_fence_after() {
    asm volatile("tcgen05.fence::after_thread_sync;" ::: "memory");
}
__device__ __forceinline__ void tc_fence_before() {
    asm volatile("tcgen05.fence::before_thread_sync;" ::: "memory");
}
__device__ __forceinline__ void tc_wait_ld() {
    asm volatile("tcgen05.wait::ld.sync.aligned;" ::: "memory");
}
__device__ __forceinline__ void fence_proxy_async_cta() {
    asm volatile("fence.proxy.async.shared::cta;" ::: "memory");
}
// dense fp8 MMA (kind::f8f6f4), cta_group::2
__device__ __forceinline__ void mma_f8_ss_cg2(uint32_t d, uint64_t a, uint64_t b, uint32_t idesc, int acc) {
    asm volatile("{ .reg .pred p; setp.ne.u32 p, %4, 0;\n"
                 "tcgen05.mma.cta_group::2.kind::f8f6f4 [%0], %1, %2, %3, {%5,%5,%5,%5,%5,%5,%5,%5}, p; }"
                 :: "r"(d), "l"(a), "l"(b), "r"(idesc), "r"(acc), "r"(0u) : "memory");
}
__device__ __forceinline__ void ldtm_x32(uint32_t* r, uint32_t addr) {
    asm volatile("tcgen05.ld.sync.aligned.32x32b.x32.b32 "
                 "{%0,%1,%2,%3,%4,%5,%6,%7,%8,%9,%10,%11,%12,%13,%14,%15,"
                 "%16,%17,%18,%19,%20,%21,%22,%23,%24,%25,%26,%27,%28,%29,%30,%31}, [%32];"
                 : "=r"(r[0]), "=r"(r[1]), "=r"(r[2]), "=r"(r[3]), "=r"(r[4]), "=r"(r[5]),
                   "=r"(r[6]), "=r"(r[7]), "=r"(r[8]), "=r"(r[9]), "=r"(r[10]), "=r"(r[11]),
                   "=r"(r[12]), "=r"(r[13]), "=r"(r[14]), "=r"(r[15]), "=r"(r[16]), "=r"(r[17]),
                   "=r"(r[18]), "=r"(r[19]), "=r"(r[20]), "=r"(r[21]), "=r"(r[22]), "=r"(r[23]),
                   "=r"(r[24]), "=r"(r[25]), "=r"(r[26]), "=r"(r[27]), "=r"(r[28]), "=r"(r[29]),
                   "=r"(r[30]), "=r"(r[31])
                 : "r"(addr));
}
__device__ __forceinline__ void cluster_sync() {
    asm volatile("barrier.cluster.arrive.aligned;" ::: "memory");
    asm volatile("barrier.cluster.wait.aligned;" ::: "memory");
}
#endif  // HAS_TC

// ---------------------------------------------------------------------------
// Kernel 1: L2-normalize rows, scale by 64, emit e4m3. (unchanged)
// ---------------------------------------------------------------------------
__global__ void __launch_bounds__(256, 4)
normalize_kernel(const float* __restrict__ z1, const float* __restrict__ z2)
{
    int gw   = blockIdx.x * 8 + (threadIdx.x >> 5);
    int lane = threadIdx.x & 31;
    int r    = gw * 2;
    int mat  = r >> 12;
    int row0 = r & (N_ROWS - 1);
    const float* src = mat ? z2 : z1;
    unsigned char* dst = mat ? g_z2q : g_z1q;

    const float4* sa = reinterpret_cast<const float4*>(src + (size_t)row0 * D_DIM);
    const float4* sb = reinterpret_cast<const float4*>(src + (size_t)(row0 + 1) * D_DIM);

    float ss0 = 0.f, ss1 = 0.f;
    #pragma unroll
    for (int j = 0; j < 8; j++) {
        float4 a = sa[j * 32 + lane];
        float4 b = sb[j * 32 + lane];
        ss0 += a.x * a.x + a.y * a.y + a.z * a.z + a.w * a.w;
        ss1 += b.x * b.x + b.y * b.y + b.z * b.z + b.w * b.w;
    }
    #pragma unroll
    for (int o = 16; o > 0; o >>= 1) {
        ss0 += __shfl_xor_sync(0xffffffffu, ss0, o);
        ss1 += __shfl_xor_sync(0xffffffffu, ss1, o);
    }
    float inv0 = QSCALE * rsqrtf(fmaxf(ss0, 1e-24f));
    float inv1 = QSCALE * rsqrtf(fmaxf(ss1, 1e-24f));

    uint32_t* d0 = reinterpret_cast<uint32_t*>(dst + (size_t)row0 * D_DIM);
    uint32_t* d1 = reinterpret_cast<uint32_t*>(dst + (size_t)(row0 + 1) * D_DIM);
    #pragma unroll
    for (int j = 0; j < 8; j++) {
        float4 a = sa[j * 32 + lane];
        float4 b = sb[j * 32 + lane];
        uint32_t alo = __nv_cvt_float2_to_fp8x2(make_float2(a.x * inv0, a.y * inv0), __NV_SATFINITE, __NV_E4M3);
        uint32_t ahi = __nv_cvt_float2_to_fp8x2(make_float2(a.z * inv0, a.w * inv0), __NV_SATFINITE, __NV_E4M3);
        uint32_t blo = __nv_cvt_float2_to_fp8x2(make_float2(b.x * inv1, b.y * inv1), __NV_SATFINITE, __NV_E4M3);
        uint32_t bhi = __nv_cvt_float2_to_fp8x2(make_float2(b.z * inv1, b.w * inv1), __NV_SATFINITE, __NV_E4M3);
        d0[j * 32 + lane] = (alo & 0xFFFFu) | (ahi << 16);
        d1[j * 32 + lane] = (blo & 0xFFFFu) | (bhi << 16);
    }
}

// epilogue compute on one 32-reg LDTM buffer
#define EPI_BLOCK(RBUF, COLBASE)                                             \
    do {                                                                     \
        _Pragma("unroll")                                                    \
        for (int q = 0; q < 32; q += 4) {                                    \
            s0 += ex2f(__uint_as_float((RBUF)[q    ]) * K1Q);                \
            s1 += ex2f(__uint_as_float((RBUF)[q + 1]) * K1Q);                \
            s2 += ex2f(__uint_as_float((RBUF)[q + 2]) * K1Q);                \
            s3 += ex2f(__uint_as_float((RBUF)[q + 3]) * K1Q);                \
        }                                                                    \
        if (hasD && ((tgtC >> 5) == (COLBASE) / 32))                         \
            dval = __uint_as_float((RBUF)[tgtC & 31]);                       \
    } while (0)

// ---------------------------------------------------------------------------
// Kernel 2: persistent cg2 tcgen05 FP8 GEMM — B panel SMEM-resident,
// software-pipelined epilogue (LDTM of next 64 cols overlaps MUFU of current).
// grid = 128 CTAs (64 clusters of 2) x 192 threads.
// warps 0-3: epilogue, warp 4: TMA (both ranks), warp 5: MMA (rank 0)
// ---------------------------------------------------------------------------
__global__ void __launch_bounds__(192, 1)
#if HAS_TC
__cluster_dims__(2, 1, 1)
#endif
gemm_lse_tc_kernel(const __grid_constant__ CUtensorMap tmA,
                   const __grid_constant__ CUtensorMap tmB)
{
#if HAS_TC
    extern __shared__ char smem[];
    const uint32_t sb = smem_u32(smem);
    const int tid  = threadIdx.x;
    const int warp = tid >> 5;
    const int lane = tid & 31;
    const int cid  = blockIdx.x >> 1;
    const int rank = blockIdx.x & 1;

    if (warp == 5) tc_alloc_cg2(sb + SMEM_TMEM, 512);
    if (tid == 0) {
        #pragma unroll
        for (int s = 0; s < STAGES; s++) {
            mbar_init(sb + SMEM_FULL  + s * 8, 1);
            mbar_init(sb + SMEM_EMPTY + s * 8, 1);
        }
        #pragma unroll
        for (int c = 0; c < NUM_CHUNKS; c++)
            mbar_init(sb + SMEM_BFULL + c * 8, 1);
        mbar_init(sb + SMEM_TDONE,     1);
        mbar_init(sb + SMEM_TDONE + 8, 1);
        mbar_init(sb + SMEM_DFREE,     8);           // 4 warps x 2 CTAs
        mbar_init(sb + SMEM_DFREE + 8, 8);
        fence_proxy_async_cta();
    }
    __syncthreads();
    cluster_sync();   // peer barriers + TMEM alloc visible before multicast traffic

    uint32_t tbase;
    asm volatile("ld.shared.b32 %0, [%1];" : "=r"(tbase) : "r"(sb + SMEM_TMEM));

    if (warp == 4) {
        // ---- TMA producer (both ranks, one elected thread each) ----
        if (elect_one()) {
            // B panel: this CTA's 128 cols, chunk-granular barriers
            int bRow = ((cid & 15) << 8) + rank * 128;
            #pragma unroll
            for (int ch = 0; ch < NUM_CHUNKS; ch++) {
                if (rank == 0)
                    mbar_expect_tx(sb + SMEM_BFULL + ch * 8, B_CHUNK_EXPECT);
                tma2d_cg2(sb + SMEM_B + ch * B_CHUNK_BYTES, &tmB,
                          ch * CHUNK_K, bRow, sb + SMEM_BFULL + ch * 8);
            }
            // A stream
            int st = 0, ph = 1;
            for (int i = 0; i < TILES_PER_CL; i++) {
                int t = cid + i * NUM_CLUSTERS;
                int aRow = ((t >> 4) << 8) + rank * 128;
                for (int ch = 0; ch < NUM_CHUNKS; ch++) {
                    mbar_wait_rlx(sb + SMEM_EMPTY + st * 8, ph);
                    if (rank == 0)
                        mbar_expect_tx(sb + SMEM_FULL + st * 8, A_EXPECT);
                    tma2d_cg2(sb + SMEM_A + st * A_STAGE_BYTES, &tmA,
                              ch * CHUNK_K, aRow, sb + SMEM_FULL + st * 8);
                    if (++st == STAGES) { st = 0; ph ^= 1; }
                }
            }
        }
    } else if (warp == 5) {
        // ---- MMA issue (leader CTA only) ----
        if (rank == 0) {
            int st = 0, ph = 0;
            int phw[2] = {1, 1};
            for (int i = 0; i < TILES_PER_CL; i++) {
                int p = i & 1;
                mbar_wait_rlx(sb + SMEM_DFREE + p * 8, phw[p]);
                phw[p] ^= 1;
                uint32_t d = tbase + p * TILE;
                for (int ch = 0; ch < NUM_CHUNKS; ch++) {
                    if (i == 0)   // B chunk only needs to land once
                        mbar_wait_acq(sb + SMEM_BFULL + ch * 8, 0);
                    mbar_wait_acq(sb + SMEM_FULL + st * 8, ph);
                    if (elect_one()) {
                        uint32_t aB = sb + SMEM_A + st * A_STAGE_BYTES;
                        uint32_t bB = sb + SMEM_B + ch * B_CHUNK_BYTES;
                        uint64_t aD = DESC_BASE | (uint64_t)((aB >> 4) & 0x3FFF);
                        uint64_t bD = DESC_BASE | (uint64_t)((bB >> 4) & 0x3FFF);
                        #pragma unroll
                        for (int j = 0; j < 4; j++)   // K=32 per MMA (2 desc units)
                            mma_f8_ss_cg2(d, aD + j * 2, bD + j * 2, MMA_IDESC, (ch > 0) | (j > 0));
                        tc_commit_mc_cg2(sb + SMEM_EMPTY + st * 8);
                    }
                    if (++st == STAGES) { st = 0; ph ^= 1; }
                }
                if (elect_one()) tc_commit_mc_cg2(sb + SMEM_TDONE + p * 8);
            }
        }
    } else {
        // ---- epilogue warps 0..3, software-pipelined LDTM ----
        const float K1Q   = 20.609929155556624f / 4096.0f;   // log2(e)/0.07/QSCALE^2
        const float INVTQ = 14.285714285714286f / 4096.0f;   // 1/0.07/QSCALE^2
        int phe[2] = {0, 0};
        for (int i = 0; i < TILES_PER_CL; i++) {
            int p = i & 1;
            int t = cid + i * NUM_CLUSTERS;
            int rowBase = (t >> 4) << 8;
            int colBase = (t & 15) << 8;
            mbar_wait_acq(sb + SMEM_TDONE + p * 8, phe[p]);
            phe[p] ^= 1;
            tc_fence_after();

            int grow = rowBase + rank * 128 + warp * 32 + lane;
            int tgtC = grow - colBase;
            bool hasD = (tgtC >= 0) && (tgtC < TILE);
            float dval = 0.f;
            float s0 = 0.f, s1 = 0.f, s2 = 0.f, s3 = 0.f;
            const uint32_t dbase = tbase + p * TILE;

            uint32_t rA0[32], rA1[32], rB0[32], rB1[32];

            // preload pair 0 (cols 0..63)
            ldtm_x32(rA0, dbase + 0);
            ldtm_x32(rA1, dbase + 32);
            tc_wait_ld();
            // pair 0: prefetch pair 1, compute pair 0, then wait
            ldtm_x32(rB0, dbase + 64);
            ldtm_x32(rB1, dbase + 96);
            EPI_BLOCK(rA0, 0);
            EPI_BLOCK(rA1, 32);
            tc_wait_ld();
            // pair 1: prefetch pair 2 into A regs, compute B, wait
            ldtm_x32(rA0, dbase + 128);
            ldtm_x32(rA1, dbase + 160);
            EPI_BLOCK(rB0, 64);
            EPI_BLOCK(rB1, 96);
            tc_wait_ld();
            // pair 2: prefetch pair 3 into B regs, compute A, wait
            ldtm_x32(rB0, dbase + 192);
            ldtm_x32(rB1, dbase + 224);
            EPI_BLOCK(rA0, 128);
            EPI_BLOCK(rA1, 160);
            tc_wait_ld();
            // pair 3: compute B (nothing left to prefetch)
            EPI_BLOCK(rB0, 192);
            EPI_BLOCK(rB1, 224);

            tc_fence_before();
            __syncwarp();
            if (lane == 0) mbar_arrive_leader(sb + SMEM_DFREE + p * 8);

            g_partial[(size_t)grow * NT + (t & 15)] = (s0 + s1) + (s2 + s3);
            if (hasD) g_diag[grow] = dval * INVTQ;
        }
    }

    __syncthreads();
    if (warp == 5) {
        tc_relinq_cg2();
        tc_dealloc_cg2(tbase, 512);
    }
    cluster_sync();
#endif  // HAS_TC
}

// ---------------------------------------------------------------------------
// Kernel 3: per-row loss + last-block final reduce (threadfence reduction).
// ---------------------------------------------------------------------------
__global__ void __launch_bounds__(128, 1) rowloss_kernel(float* __restrict__ out)
{
    int tid = threadIdx.x;
    int row = blockIdx.x * 128 + tid;
    const float4* p = reinterpret_cast<const float4*>(g_partial + (size_t)row * NT);
    float4 a = p[0], b = p[1], c = p[2], d = p[3];
    float s = (((a.x + a.y) + (a.z + a.w)) + ((b.x + b.y) + (b.z + b.w)))
            + (((c.x + c.y) + (c.z + c.w)) + ((d.x + d.y) + (d.z + d.w)));
    double loss = (double)(logf(s) - g_diag[row]);

    #pragma unroll
    for (int o = 16; o > 0; o >>= 1) loss += __shfl_xor_sync(0xffffffffu, loss, o);
    __shared__ double sh[4];
    __shared__ bool isLast;
    if ((tid & 31) == 0) sh[tid >> 5] = loss;
    __syncthreads();
    if (tid == 0) {
        g_blocksum[blockIdx.x] = sh[0] + sh[1] + sh[2] + sh[3];
        __threadfence();
        unsigned o = atomicAdd(&g_ctr, 1u);
        isLast = (o == 31u);
    }
    __syncthreads();
    if (isLast && tid < 32) {
        double x = g_blocksum[tid];
        #pragma unroll
        for (int o = 16; o > 0; o >>= 1) x += __shfl_xor_sync(0xffffffffu, x, o);
        if (tid == 0) {
            out[0] = (float)(x / (double)N_ROWS);
            g_ctr = 0u;   // reset for next graph replay
        }
    }
}

// ---------------------------------------------------------------------------
extern "C" void kernel_launch(void* const* d_in, const int* in_sizes, int n_in,
                              void* d_out, int out_size)
{
    const float* z1 = (const float*)d_in[0];
    const float* z2 = (const float*)d_in[1];
    float* out = (float*)d_out;

    void *pa = nullptr, *pb = nullptr;
    cudaGetSymbolAddress(&pa, g_z1q);
    cudaGetSymbolAddress(&pb, g_z2q);

    typedef CUresult (*EncFn)(CUtensorMap*, CUtensorMapDataType, cuuint32_t, void*,
                              const cuuint64_t*, const cuuint64_t*, const cuuint32_t*,
                              const cuuint32_t*, CUtensorMapInterleave, CUtensorMapSwizzle,
                              CUtensorMapL2promotion, CUtensorMapFloatOOBfill);
    void* h = dlopen("libcuda.so.1", RTLD_NOW | RTLD_GLOBAL);
    if (!h) h = dlopen("libcuda.so", RTLD_NOW | RTLD_GLOBAL);
    EncFn enc = h ? (EncFn)dlsym(h, "cuTensorMapEncodeTiled") : nullptr;

    CUtensorMap tmA = {}, tmB = {};
    cuuint64_t dims[2]    = {D_DIM, N_ROWS};
    cuuint64_t strides[1] = {D_DIM};
    cuuint32_t box[2]     = {CHUNK_K, 128};
    cuuint32_t es[2]      = {1, 1};
    if (enc) {
        enc(&tmA, CU_TENSOR_MAP_DATA_TYPE_UINT8, 2, pa, dims, strides, box, es,
            CU_TENSOR_MAP_INTERLEAVE_NONE, CU_TENSOR_MAP_SWIZZLE_128B,
            CU_TENSOR_MAP_L2_PROMOTION_L2_128B, CU_TENSOR_MAP_FLOAT_OOB_FILL_NONE);
        enc(&tmB, CU_TENSOR_MAP_DATA_TYPE_UINT8, 2, pb, dims, strides, box, es,
            CU_TENSOR_MAP_INTERLEAVE_NONE, CU_TENSOR_MAP_SWIZZLE_128B,
            CU_TENSOR_MAP_L2_PROMOTION_L2_128B, CU_TENSOR_MAP_FLOAT_OOB_FILL_NONE);
    }

    cudaFuncSetAttribute(gemm_lse_tc_kernel,
                         cudaFuncAttributeMaxDynamicSharedMemorySize, SMEM_TOTAL);

    normalize_kernel<<<512, 256>>>(z1, z2);
    gemm_lse_tc_kernel<<<GRID_GEMM, 192, SMEM_TOTAL>>>(tmA, tmB);
    rowloss_kernel<<<32, 128>>>(out);
}

// round 12
// speedup vs baseline: 1.1301x; 1.1301x over previous
#include <cuda_runtime.h>
#include <cuda.h>
#include <cuda_bf16.h>
#include <cuda_fp8.h>
#include <math.h>
#include <stdint.h>
#include <dlfcn.h>

// ---- feature probe: tcgen05/cg2 need arch-specific (sm_103a) pass ----
#if defined(__CUDA_ARCH_FEAT_SM103_ALL) || \
    (defined(__CUDA_ARCH_SPECIFIC__) && (__CUDA_ARCH_SPECIFIC__ == 1030))
#define HAS_TC 1
#else
#define HAS_TC 0
#endif

// ---------------- problem constants ----------------
#define N_ROWS 4096
#define D_DIM  1024
#define TILE   256                         // 256x256 output tiles (cg2 pair)
#define NT     (N_ROWS / TILE)             // 16 column tiles -> 16 partials/row
#define NUM_TILES (NT * NT)                // 256
#define GRID_GEMM 128                      // 64 clusters of 2
#define NUM_CLUSTERS (GRID_GEMM / 2)       // 64
#define TILES_PER_CL (NUM_TILES / NUM_CLUSTERS)  // 4 (same col panel per cluster)
#define NUM_CHUNKS 8                       // B chunks: 128 K-elems each
#define STAGES 3                           // A stages (32KB each = 256 K-elems)
#define STAGES_PER_TILE 4                  // 4 x 256 K-elems = K 1024

// FP8 scaling: store 64*v (e4m3), logits = acc / 4096
#define QSCALE 64.0f

// SMEM layout (per CTA)
#define SMEM_TMEM   0
#define SMEM_FULL   8       // 3 x 8B  (A stage full, leader)
#define SMEM_EMPTY  32      // 3 x 8B  (A stage empty, multicast)
#define SMEM_BFULL  56      // 8 x 8B  (B chunk full, leader)
#define SMEM_TDONE  120     // 2 x 8B  (tile MMA done, multicast)
#define SMEM_DFREE  136     // 2 x 8B  (TMEM buffer free, leader, count 8)
#define SMEM_B      1024                    // B panel: 8 chunks x 16KB = 128KB
#define B_CHUNK_BYTES 16384
#define SMEM_A      (SMEM_B + NUM_CHUNKS * B_CHUNK_BYTES)   // 132096
#define A_STAGE_BYTES 32768                 // two 16KB SW128 sub-tiles
#define SMEM_TOTAL  (SMEM_A + STAGES * A_STAGE_BYTES)       // 230400
#define A_EXPECT (2 * A_STAGE_BYTES)        // both CTAs -> leader barrier (64KB)
#define B_CHUNK_EXPECT (2 * B_CHUNK_BYTES)  // both CTAs' halves of one chunk

// idesc: kind::f8f6f4, dtype F32 (bits[4:5]=1), atype=btype=E4M3 (0),
// N=256 (bits[17:23)), M_total=256 (bits[24:29))
#define MMA_IDESC ((1u<<4)|((TILE/8)<<17)|((TILE/16)<<24))

// SW128 K-major smem descriptor base (layout=2, version=1, SBO=64, LBO=1)
static __device__ constexpr uint64_t DESC_BASE =
    (uint64_t(2) << 61) | (uint64_t(1) << 46) | (uint64_t(64) << 32) | (uint64_t(1) << 16);

// ---------------- device scratch (no cudaMalloc allowed) ----------------
__device__ __align__(1024) unsigned char g_z1q[N_ROWS * D_DIM];
__device__ __align__(1024) unsigned char g_z2q[N_ROWS * D_DIM];
__device__ float    g_partial[N_ROWS * NT];
__device__ float    g_diag[N_ROWS];
__device__ double   g_blocksum[32];
__device__ unsigned g_ctr;    // zero-init; self-resetting each call

// ---------------- PTX helpers ----------------
__device__ __forceinline__ uint32_t smem_u32(const void* p) {
    uint32_t a;
    asm("{ .reg .u64 t; cvta.to.shared.u64 t, %1; cvt.u32.u64 %0, t; }" : "=r"(a) : "l"(p));
    return a;
}
__device__ __forceinline__ float ex2f(float x) {
    float y; asm("ex2.approx.f32 %0, %1;" : "=f"(y) : "f"(x)); return y;
}

#if HAS_TC
__device__ __forceinline__ uint32_t elect_one() {
    uint32_t p;
    asm volatile("{ .reg .pred p; elect.sync _|p, 0xFFFFFFFF; selp.b32 %0,1,0,p; }" : "=r"(p));
    return p;
}
__device__ __forceinline__ void mbar_init(uint32_t a, uint32_t cnt) {
    asm volatile("mbarrier.init.shared.b64 [%0], %1;" :: "r"(a), "r"(cnt) : "memory");
}
__device__ __forceinline__ void mbar_expect_tx(uint32_t a, uint32_t bytes) {
    asm volatile("mbarrier.arrive.expect_tx.shared.b64 _, [%0], %1;" :: "r"(a), "r"(bytes) : "memory");
}
__device__ __forceinline__ void mbar_arrive_leader(uint32_t a) {
    asm volatile("{ .reg .b32 la; and.b32 la, %0, 0xFEFFFFFF;\n"
                 "mbarrier.arrive.shared::cluster.b64 _, [la]; }" :: "r"(a) : "memory");
}
__device__ __forceinline__ void mbar_wait_acq(uint32_t a, uint32_t ph) {
    asm volatile("{ .reg .pred P;\n"
                 "W_%=: mbarrier.try_wait.parity.acquire.cta.shared::cta.b64 P, [%0], %1;\n"
                 "@!P bra W_%=; }" :: "r"(a), "r"(ph) : "memory");
}
__device__ __forceinline__ void mbar_wait_rlx(uint32_t a, uint32_t ph) {
    asm volatile("{ .reg .pred P;\n"
                 "W_%=: mbarrier.try_wait.parity.relaxed.cta.shared::cta.b64 P, [%0], %1;\n"
                 "@!P bra W_%=; }" :: "r"(a), "r"(ph) : "memory");
}
// cg2 TMA: both CTAs execute; complete_tx targets the LEADER's barrier (bit 24 cleared)
__device__ __forceinline__ void tma2d_cg2(uint32_t dst, const CUtensorMap* m, int x, int y, uint32_t mbar) {
    asm volatile("{ .reg .b32 lb; and.b32 lb, %4, 0xFEFFFFFF;\n"
                 "cp.async.bulk.tensor.2d.cta_group::2.shared::cluster.global.tile.mbarrier::complete_tx::bytes "
                 "[%0], [%1, {%2, %3}], [lb]; }"
                 :: "r"(dst), "l"(m), "r"(x), "r"(y), "r"(mbar) : "memory");
}
__device__ __forceinline__ void tc_alloc_cg2(uint32_t smem_res, uint32_t ncols) {
    asm volatile("tcgen05.alloc.cta_group::2.sync.aligned.shared::cta.b32 [%0], %1;"
                 :: "r"(smem_res), "r"(ncols) : "memory");
}
__device__ __forceinline__ void tc_dealloc_cg2(uint32_t tmem, uint32_t ncols) {
    asm volatile("tcgen05.dealloc.cta_group::2.sync.aligned.b32 %0, %1;" :: "r"(tmem), "r"(ncols));
}
__device__ __forceinline__ void tc_relinq_cg2() {
    asm volatile("tcgen05.relinquish_alloc_permit.cta_group::2.sync.aligned;");
}
__device__ __forceinline__ void tc_commit_mc_cg2(uint32_t mbar) {
    asm volatile("tcgen05.commit.cta_group::2.mbarrier::arrive::one.shared::cluster.multicast::cluster.b64 [%0], %1;"
                 :: "r"(mbar), "h"((uint16_t)3) : "memory");
}
__device__ __forceinline__ void tc_fence_after() {
    asm volatile("tcgen05.fence::after_thread_sync;" ::: "memory");
}
__device__ __forceinline__ void tc_fence_before() {
    asm volatile("tcgen05.fence::before_thread_sync;" ::: "memory");
}
__device__ __forceinline__ void tc_wait_ld() {
    asm volatile("tcgen05.wait::ld.sync.aligned;" ::: "memory");
}
__device__ __forceinline__ void fence_proxy_async_cta() {
    asm volatile("fence.proxy.async.shared::cta;" ::: "memory");
}
// dense fp8 MMA (kind::f8f6f4), cta_group::2
__device__ __forceinline__ void mma_f8_ss_cg2(uint32_t d, uint64_t a, uint64_t b, uint32_t idesc, int acc) {
    asm volatile("{ .reg .pred p; setp.ne.u32 p, %4, 0;\n"
                 "tcgen05.mma.cta_group::2.kind::f8f6f4 [%0], %1, %2, %3, {%5,%5,%5,%5,%5,%5,%5,%5}, p; }"
                 :: "r"(d), "l"(a), "l"(b), "r"(idesc), "r"(acc), "r"(0u) : "memory");
}
__device__ __forceinline__ void ldtm_x32(uint32_t* r, uint32_t addr) {
    asm volatile("tcgen05.ld.sync.aligned.32x32b.x32.b32 "
                 "{%0,%1,%2,%3,%4,%5,%6,%7,%8,%9,%10,%11,%12,%13,%14,%15,"
                 "%16,%17,%18,%19,%20,%21,%22,%23,%24,%25,%26,%27,%28,%29,%30,%31}, [%32];"
                 : "=r"(r[0]), "=r"(r[1]), "=r"(r[2]), "=r"(r[3]), "=r"(r[4]), "=r"(r[5]),
                   "=r"(r[6]), "=r"(r[7]), "=r"(r[8]), "=r"(r[9]), "=r"(r[10]), "=r"(r[11]),
                   "=r"(r[12]), "=r"(r[13]), "=r"(r[14]), "=r"(r[15]), "=r"(r[16]), "=r"(r[17]),
                   "=r"(r[18]), "=r"(r[19]), "=r"(r[20]), "=r"(r[21]), "=r"(r[22]), "=r"(r[23]),
                   "=r"(r[24]), "=r"(r[25]), "=r"(r[26]), "=r"(r[27]), "=r"(r[28]), "=r"(r[29]),
                   "=r"(r[30]), "=r"(r[31])
                 : "r"(addr));
}
__device__ __forceinline__ void cluster_sync() {
    asm volatile("barrier.cluster.arrive.aligned;" ::: "memory");
    asm volatile("barrier.cluster.wait.aligned;" ::: "memory");
}
#endif  // HAS_TC

// ---------------------------------------------------------------------------
// Kernel 1: L2-normalize rows, scale by 64, emit e4m3. (unchanged, 9.6us)
// ---------------------------------------------------------------------------
__global__ void __launch_bounds__(256, 4)
normalize_kernel(const float* __restrict__ z1, const float* __restrict__ z2)
{
    int gw   = blockIdx.x * 8 + (threadIdx.x >> 5);
    int lane = threadIdx.x & 31;
    int r    = gw * 2;
    int mat  = r >> 12;
    int row0 = r & (N_ROWS - 1);
    const float* src = mat ? z2 : z1;
    unsigned char* dst = mat ? g_z2q : g_z1q;

    const float4* sa = reinterpret_cast<const float4*>(src + (size_t)row0 * D_DIM);
    const float4* sb = reinterpret_cast<const float4*>(src + (size_t)(row0 + 1) * D_DIM);

    float ss0 = 0.f, ss1 = 0.f;
    #pragma unroll
    for (int j = 0; j < 8; j++) {
        float4 a = sa[j * 32 + lane];
        float4 b = sb[j * 32 + lane];
        ss0 += a.x * a.x + a.y * a.y + a.z * a.z + a.w * a.w;
        ss1 += b.x * b.x + b.y * b.y + b.z * b.z + b.w * b.w;
    }
    #pragma unroll
    for (int o = 16; o > 0; o >>= 1) {
        ss0 += __shfl_xor_sync(0xffffffffu, ss0, o);
        ss1 += __shfl_xor_sync(0xffffffffu, ss1, o);
    }
    float inv0 = QSCALE * rsqrtf(fmaxf(ss0, 1e-24f));
    float inv1 = QSCALE * rsqrtf(fmaxf(ss1, 1e-24f));

    uint32_t* d0 = reinterpret_cast<uint32_t*>(dst + (size_t)row0 * D_DIM);
    uint32_t* d1 = reinterpret_cast<uint32_t*>(dst + (size_t)(row0 + 1) * D_DIM);
    #pragma unroll
    for (int j = 0; j < 8; j++) {
        float4 a = sa[j * 32 + lane];
        float4 b = sb[j * 32 + lane];
        uint32_t alo = __nv_cvt_float2_to_fp8x2(make_float2(a.x * inv0, a.y * inv0), __NV_SATFINITE, __NV_E4M3);
        uint32_t ahi = __nv_cvt_float2_to_fp8x2(make_float2(a.z * inv0, a.w * inv0), __NV_SATFINITE, __NV_E4M3);
        uint32_t blo = __nv_cvt_float2_to_fp8x2(make_float2(b.x * inv1, b.y * inv1), __NV_SATFINITE, __NV_E4M3);
        uint32_t bhi = __nv_cvt_float2_to_fp8x2(make_float2(b.z * inv1, b.w * inv1), __NV_SATFINITE, __NV_E4M3);
        d0[j * 32 + lane] = (alo & 0xFFFFu) | (ahi << 16);
        d1[j * 32 + lane] = (blo & 0xFFFFu) | (bhi << 16);
    }
}

// ---------------------------------------------------------------------------
// Kernel 2: persistent cg2 tcgen05 FP8 GEMM — B resident, 32KB A stages
// (one barrier per 256 K-elems: half the mbarrier waits on MMA + TMA warps).
// Epilogue = proven R8 paired-LDTM form.
// grid = 128 CTAs (64 clusters of 2) x 192 threads.
// ---------------------------------------------------------------------------
__global__ void __launch_bounds__(192, 1)
#if HAS_TC
__cluster_dims__(2, 1, 1)
#endif
gemm_lse_tc_kernel(const __grid_constant__ CUtensorMap tmA,
                   const __grid_constant__ CUtensorMap tmB)
{
#if HAS_TC
    extern __shared__ char smem[];
    const uint32_t sb = smem_u32(smem);
    const int tid  = threadIdx.x;
    const int warp = tid >> 5;
    const int lane = tid & 31;
    const int cid  = blockIdx.x >> 1;
    const int rank = blockIdx.x & 1;

    if (warp == 5) tc_alloc_cg2(sb + SMEM_TMEM, 512);
    if (tid == 0) {
        #pragma unroll
        for (int s = 0; s < STAGES; s++) {
            mbar_init(sb + SMEM_FULL  + s * 8, 1);
            mbar_init(sb + SMEM_EMPTY + s * 8, 1);
        }
        #pragma unroll
        for (int c = 0; c < NUM_CHUNKS; c++)
            mbar_init(sb + SMEM_BFULL + c * 8, 1);
        mbar_init(sb + SMEM_TDONE,     1);
        mbar_init(sb + SMEM_TDONE + 8, 1);
        mbar_init(sb + SMEM_DFREE,     8);           // 4 warps x 2 CTAs
        mbar_init(sb + SMEM_DFREE + 8, 8);
        fence_proxy_async_cta();
    }
    __syncthreads();
    cluster_sync();   // peer barriers + TMEM alloc visible before multicast traffic

    uint32_t tbase;
    asm volatile("ld.shared.b32 %0, [%1];" : "=r"(tbase) : "r"(sb + SMEM_TMEM));

    if (warp == 4) {
        // ---- TMA producer (both ranks, one elected thread each) ----
        if (elect_one()) {
            // B panel: this CTA's 128 cols, chunk-granular barriers
            int bRow = ((cid & 15) << 8) + rank * 128;
            #pragma unroll
            for (int ch = 0; ch < NUM_CHUNKS; ch++) {
                if (rank == 0)
                    mbar_expect_tx(sb + SMEM_BFULL + ch * 8, B_CHUNK_EXPECT);
                tma2d_cg2(sb + SMEM_B + ch * B_CHUNK_BYTES, &tmB,
                          ch * 128, bRow, sb + SMEM_BFULL + ch * 8);
            }
            // A stream: 32KB stages, two TMA boxes per stage, one barrier
            int st = 0, ph = 1;
            for (int i = 0; i < TILES_PER_CL; i++) {
                int t = cid + i * NUM_CLUSTERS;
                int aRow = ((t >> 4) << 8) + rank * 128;
                for (int s = 0; s < STAGES_PER_TILE; s++) {
                    mbar_wait_rlx(sb + SMEM_EMPTY + st * 8, ph);
                    if (rank == 0)
                        mbar_expect_tx(sb + SMEM_FULL + st * 8, A_EXPECT);
                    uint32_t dst = sb + SMEM_A + st * A_STAGE_BYTES;
                    tma2d_cg2(dst,         &tmA, s * 256,       aRow, sb + SMEM_FULL + st * 8);
                    tma2d_cg2(dst + 16384, &tmA, s * 256 + 128, aRow, sb + SMEM_FULL + st * 8);
                    if (++st == STAGES) { st = 0; ph ^= 1; }
                }
            }
        }
    } else if (warp == 5) {
        // ---- MMA issue (leader CTA only): 4 waits + 4 commits per tile ----
        if (rank == 0) {
            int st = 0, ph = 0;
            int phw[2] = {1, 1};
            for (int i = 0; i < TILES_PER_CL; i++) {
                int p = i & 1;
                mbar_wait_rlx(sb + SMEM_DFREE + p * 8, phw[p]);
                phw[p] ^= 1;
                uint32_t d = tbase + p * TILE;
                for (int s = 0; s < STAGES_PER_TILE; s++) {
                    if (i == 0) {   // B chunks land once
                        mbar_wait_acq(sb + SMEM_BFULL + (2 * s)     * 8, 0);
                        mbar_wait_acq(sb + SMEM_BFULL + (2 * s + 1) * 8, 0);
                    }
                    mbar_wait_acq(sb + SMEM_FULL + st * 8, ph);
                    if (elect_one()) {
                        uint32_t aB = sb + SMEM_A + st * A_STAGE_BYTES;
                        #pragma unroll
                        for (int half = 0; half < 2; half++) {
                            uint64_t aD = DESC_BASE |
                                (uint64_t)(((aB + half * 16384) >> 4) & 0x3FFF);
                            uint64_t bD = DESC_BASE |
                                (uint64_t)(((sb + SMEM_B + (2 * s + half) * B_CHUNK_BYTES) >> 4) & 0x3FFF);
                            #pragma unroll
                            for (int j = 0; j < 4; j++)   // K=32 per MMA
                                mma_f8_ss_cg2(d, aD + j * 2, bD + j * 2, MMA_IDESC,
                                              (s > 0) | (half > 0) | (j > 0));
                        }
                        tc_commit_mc_cg2(sb + SMEM_EMPTY + st * 8);
                    }
                    if (++st == STAGES) { st = 0; ph ^= 1; }
                }
                if (elect_one()) tc_commit_mc_cg2(sb + SMEM_TDONE + p * 8);
            }
        }
    } else {
        // ---- epilogue warps 0..3 (R8 form: paired LDTM, one wait per 64 cols) ----
        const float K1Q   = 20.609929155556624f / 4096.0f;   // log2(e)/0.07/QSCALE^2
        const float INVTQ = 14.285714285714286f / 4096.0f;   // 1/0.07/QSCALE^2
        int phe[2] = {0, 0};
        for (int i = 0; i < TILES_PER_CL; i++) {
            int p = i & 1;
            int t = cid + i * NUM_CLUSTERS;
            int rowBase = (t >> 4) << 8;
            int colBase = (t & 15) << 8;
            mbar_wait_acq(sb + SMEM_TDONE + p * 8, phe[p]);
            phe[p] ^= 1;
            tc_fence_after();

            int grow = rowBase + rank * 128 + warp * 32 + lane;
            int tgtC = grow - colBase;
            bool hasD = (tgtC >= 0) && (tgtC < TILE);
            float dval = 0.f;
            float s0 = 0.f, s1 = 0.f, s2 = 0.f, s3 = 0.f;

            #pragma unroll
            for (int pair = 0; pair < 4; pair++) {   // 2 x 32 cols per iteration
                uint32_t r0[32], r1[32];
                ldtm_x32(r0, tbase + p * TILE + pair * 64);
                ldtm_x32(r1, tbase + p * TILE + pair * 64 + 32);
                tc_wait_ld();
                #pragma unroll
                for (int q = 0; q < 32; q += 4) {
                    s0 += ex2f(__uint_as_float(r0[q    ]) * K1Q);
                    s1 += ex2f(__uint_as_float(r0[q + 1]) * K1Q);
                    s2 += ex2f(__uint_as_float(r0[q + 2]) * K1Q);
                    s3 += ex2f(__uint_as_float(r0[q + 3]) * K1Q);
                }
                #pragma unroll
                for (int q = 0; q < 32; q += 4) {
                    s0 += ex2f(__uint_as_float(r1[q    ]) * K1Q);
                    s1 += ex2f(__uint_as_float(r1[q + 1]) * K1Q);
                    s2 += ex2f(__uint_as_float(r1[q + 2]) * K1Q);
                    s3 += ex2f(__uint_as_float(r1[q + 3]) * K1Q);
                }
                if (hasD && ((tgtC >> 6) == pair))
                    dval = (tgtC & 32) ? __uint_as_float(r1[tgtC & 31])
                                       : __uint_as_float(r0[tgtC & 31]);
            }
            tc_fence_before();
            __syncwarp();
            if (lane == 0) mbar_arrive_leader(sb + SMEM_DFREE + p * 8);

            g_partial[(size_t)grow * NT + (t & 15)] = (s0 + s1) + (s2 + s3);
            if (hasD) g_diag[grow] = dval * INVTQ;
        }
    }

    __syncthreads();
    if (warp == 5) {
        tc_relinq_cg2();
        tc_dealloc_cg2(tbase, 512);
    }
    cluster_sync();
#endif  // HAS_TC
}

// ---------------------------------------------------------------------------
// Kernel 3: per-row loss + last-block final reduce (threadfence reduction).
// ---------------------------------------------------------------------------
__global__ void __launch_bounds__(128, 1) rowloss_kernel(float* __restrict__ out)
{
    int tid = threadIdx.x;
    int row = blockIdx.x * 128 + tid;
    const float4* p = reinterpret_cast<const float4*>(g_partial + (size_t)row * NT);
    float4 a = p[0], b = p[1], c = p[2], d = p[3];
    float s = (((a.x + a.y) + (a.z + a.w)) + ((b.x + b.y) + (b.z + b.w)))
            + (((c.x + c.y) + (c.z + c.w)) + ((d.x + d.y) + (d.z + d.w)));
    double loss = (double)(logf(s) - g_diag[row]);

    #pragma unroll
    for (int o = 16; o > 0; o >>= 1) loss += __shfl_xor_sync(0xffffffffu, loss, o);
    __shared__ double sh[4];
    __shared__ bool isLast;
    if ((tid & 31) == 0) sh[tid >> 5] = loss;
    __syncthreads();
    if (tid == 0) {
        g_blocksum[blockIdx.x] = sh[0] + sh[1] + sh[2] + sh[3];
        __threadfence();
        unsigned o = atomicAdd(&g_ctr, 1u);
        isLast = (o == 31u);
    }
    __syncthreads();
    if (isLast && tid < 32) {
        double x = g_blocksum[tid];
        #pragma unroll
        for (int o = 16; o > 0; o >>= 1) x += __shfl_xor_sync(0xffffffffu, x, o);
        if (tid == 0) {
            out[0] = (float)(x / (double)N_ROWS);
            g_ctr = 0u;   // reset for next graph replay
        }
    }
}

// ---------------------------------------------------------------------------
extern "C" void kernel_launch(void* const* d_in, const int* in_sizes, int n_in,
                              void* d_out, int out_size)
{
    const float* z1 = (const float*)d_in[0];
    const float* z2 = (const float*)d_in[1];
    float* out = (float*)d_out;

    void *pa = nullptr, *pb = nullptr;
    cudaGetSymbolAddress(&pa, g_z1q);
    cudaGetSymbolAddress(&pb, g_z2q);

    typedef CUresult (*EncFn)(CUtensorMap*, CUtensorMapDataType, cuuint32_t, void*,
                              const cuuint64_t*, const cuuint64_t*, const cuuint32_t*,
                              const cuuint32_t*, CUtensorMapInterleave, CUtensorMapSwizzle,
                              CUtensorMapL2promotion, CUtensorMapFloatOOBfill);
    void* h = dlopen("libcuda.so.1", RTLD_NOW | RTLD_GLOBAL);
    if (!h) h = dlopen("libcuda.so", RTLD_NOW | RTLD_GLOBAL);
    EncFn enc = h ? (EncFn)dlsym(h, "cuTensorMapEncodeTiled") : nullptr;

    CUtensorMap tmA = {}, tmB = {};
    cuuint64_t dims[2]    = {D_DIM, N_ROWS};
    cuuint64_t strides[1] = {D_DIM};
    cuuint32_t box[2]     = {128, 128};     // 128B x 128 rows per TMA box
    cuuint32_t es[2]      = {1, 1};
    if (enc) {
        enc(&tmA, CU_TENSOR_MAP_DATA_TYPE_UINT8, 2, pa, dims, strides, box, es,
            CU_TENSOR_MAP_INTERLEAVE_NONE, CU_TENSOR_MAP_SWIZZLE_128B,
            CU_TENSOR_MAP_L2_PROMOTION_L2_128B, CU_TENSOR_MAP_FLOAT_OOB_FILL_NONE);
        enc(&tmB, CU_TENSOR_MAP_DATA_TYPE_UINT8, 2, pb, dims, strides, box, es,
            CU_TENSOR_MAP_INTERLEAVE_NONE, CU_TENSOR_MAP_SWIZZLE_128B,
            CU_TENSOR_MAP_L2_PROMOTION_L2_128B, CU_TENSOR_MAP_FLOAT_OOB_FILL_NONE);
    }

    cudaFuncSetAttribute(gemm_lse_tc_kernel,
                         cudaFuncAttributeMaxDynamicSharedMemorySize, SMEM_TOTAL);

    normalize_kernel<<<512, 256>>>(z1, z2);
    gemm_lse_tc_kernel<<<GRID_GEMM, 192, SMEM_TOTAL>>>(tmA, tmB);
    rowloss_kernel<<<32, 128>>>(out);
}